// round 4
// baseline (speedup 1.0000x reference)
#include <cuda_runtime.h>
#include <cstdint>

// ---------------- problem constants ----------------
#define D_DIM  512
#define HID    513
#define HIDP   576           // padded: 9 * 64
#define P_CTX  8192
#define KTEST  2048
#define LDEPTH 8
#define HIDP2  (HIDP*HIDP)
#define NZ     8             // split-K chunks for syrk
#define ZCHUNK (P_CTX/NZ)    // 1024
#define NTILE  9             // 576/64
#define NPAIR  45            // upper-tri tile pairs
#define KC     32            // K per chunk

// ---------------- scratch ----------------
__device__ float g_AugT [HIDP*P_CTX];     // [576][8192] transposed aug inputs
__device__ float g_Spart[NZ*NPAIR*64*64];
__device__ float g_S   [HIDP2];
__device__ float g_Wxa [HIDP2];
__device__ float g_WqT [HIDP2];
__device__ float g_WkT [HIDP2];
__device__ float g_WvP [HIDP2];
__device__ float g_F   [HIDP2];           // E^T = Wq^T Wk
__device__ float g_G   [HIDP2];
__device__ float g_T   [HIDP2];
__device__ float g_T2  [HIDP2];
__device__ float g_A   [LDEPTH*HIDP2];
__device__ float g_u   [2*HID];
__device__ float g_d   [D_DIM];

__device__ __forceinline__ uint32_t f2tf32(float x) {
    uint32_t u;
    asm("cvt.rna.tf32.f32 %0, %1;" : "=r"(u) : "f"(x));
    return u;
}

__device__ __forceinline__ void mma_tf32(float* c, const uint32_t* a, const uint32_t* b) {
    asm volatile(
        "mma.sync.aligned.m16n8k8.row.col.f32.tf32.tf32.f32 "
        "{%0,%1,%2,%3}, {%4,%5,%6,%7}, {%8,%9}, {%0,%1,%2,%3};"
        : "+f"(c[0]), "+f"(c[1]), "+f"(c[2]), "+f"(c[3])
        : "r"(a[0]), "r"(a[1]), "r"(a[2]), "r"(a[3]), "r"(b[0]), "r"(b[1]));
}

// ============ tf32 mma GEMM: acc = A · B^T  (both K-major fp32) ============
// mode 0: C = alpha*acc                (C stride HIDP, tile (by*64, bx*64))
// mode 1: C = Dm - acc                 (same addressing)
// mode 2: syrk partial: blockIdx.x = pair, blockIdx.z = split,
//         C = Spart + (z*NPAIR+pair)*4096, tile-local stride 64
__global__ __launch_bounds__(256) void mma_gemm(
    const float* __restrict__ A, int lda,
    const float* __restrict__ B, int ldb,
    float* __restrict__ C, const float* __restrict__ Dm,
    int kchunks, float alpha, int mode)
{
    __shared__ uint32_t As[2][64][36];
    __shared__ uint32_t Bs[2][64][36];

    const int tid  = threadIdx.x;
    const int wid  = tid >> 5;
    const int lane = tid & 31;

    int bm, bn;
    float* Cout = C;
    if (mode == 2) {
        int q = blockIdx.x, ti = 0, rem = q;
        while (rem >= NTILE - ti) { rem -= NTILE - ti; ti++; }
        bm = ti * 64; bn = (ti + rem) * 64;
        Cout = C + ((size_t)blockIdx.z * NPAIR + q) * 4096;
    } else {
        bm = blockIdx.y * 64; bn = blockIdx.x * 64;
    }
    const int kstart = blockIdx.z * kchunks * KC;

    const float* Abase = A + (size_t)bm * lda + kstart;
    const float* Bbase = B + (size_t)bn * ldb + kstart;

    // staging: 64x32 tile = 512 float4, 256 threads -> 2 each
    const int srow0 = tid >> 3;             // 0..31
    const int srow1 = srow0 + 32;           // 32..63
    const int sseg  = (tid & 7) * 4;        // 0,4,..28

    float4 ra0, ra1, rb0, rb1;

    auto g_load = [&](int c) {
        const float* Ap = Abase + c * KC;
        const float* Bp = Bbase + c * KC;
        ra0 = *reinterpret_cast<const float4*>(Ap + (size_t)srow0 * lda + sseg);
        ra1 = *reinterpret_cast<const float4*>(Ap + (size_t)srow1 * lda + sseg);
        rb0 = *reinterpret_cast<const float4*>(Bp + (size_t)srow0 * ldb + sseg);
        rb1 = *reinterpret_cast<const float4*>(Bp + (size_t)srow1 * ldb + sseg);
    };
    auto s_store = [&](int buf) {
        uint4 ua0 = { f2tf32(ra0.x), f2tf32(ra0.y), f2tf32(ra0.z), f2tf32(ra0.w) };
        uint4 ua1 = { f2tf32(ra1.x), f2tf32(ra1.y), f2tf32(ra1.z), f2tf32(ra1.w) };
        uint4 ub0 = { f2tf32(rb0.x), f2tf32(rb0.y), f2tf32(rb0.z), f2tf32(rb0.w) };
        uint4 ub1 = { f2tf32(rb1.x), f2tf32(rb1.y), f2tf32(rb1.z), f2tf32(rb1.w) };
        *reinterpret_cast<uint4*>(&As[buf][srow0][sseg]) = ua0;
        *reinterpret_cast<uint4*>(&As[buf][srow1][sseg]) = ua1;
        *reinterpret_cast<uint4*>(&Bs[buf][srow0][sseg]) = ub0;
        *reinterpret_cast<uint4*>(&Bs[buf][srow1][sseg]) = ub1;
    };

    // warp tiling: 2 (m) x 4 (n) warps; warp tile 32x16
    const int wm = (wid >> 2) * 32;
    const int wn = (wid & 3) * 16;
    const int gr = lane >> 2;     // 0..7
    const int gc = lane & 3;      // 0..3

    float acc[2][2][4] = {};

    g_load(0);
    s_store(0);
    __syncthreads();

    for (int c = 0; c < kchunks; c++) {
        const int buf = c & 1;
        const bool more = (c + 1 < kchunks);
        if (more) g_load(c + 1);

        #pragma unroll
        for (int s = 0; s < 4; s++) {
            const int k0 = s * 8;
            uint32_t a[2][4], b[2][2];
            #pragma unroll
            for (int tm = 0; tm < 2; tm++) {
                const int mb = wm + tm * 16;
                a[tm][0] = As[buf][mb + gr    ][k0 + gc];
                a[tm][1] = As[buf][mb + gr + 8][k0 + gc];
                a[tm][2] = As[buf][mb + gr    ][k0 + gc + 4];
                a[tm][3] = As[buf][mb + gr + 8][k0 + gc + 4];
            }
            #pragma unroll
            for (int tn = 0; tn < 2; tn++) {
                const int nb = wn + tn * 8;
                b[tn][0] = Bs[buf][nb + gr][k0 + gc];
                b[tn][1] = Bs[buf][nb + gr][k0 + gc + 4];
            }
            #pragma unroll
            for (int tm = 0; tm < 2; tm++)
                #pragma unroll
                for (int tn = 0; tn < 2; tn++)
                    mma_tf32(acc[tm][tn], a[tm], b[tn]);
        }

        if (more) {
            __syncthreads();
            s_store(buf ^ 1);
            __syncthreads();
        }
    }

    // epilogue: c0 at (gr, gc*2), c1 (gr, gc*2+1), c2 (gr+8, ..), c3
    #pragma unroll
    for (int tm = 0; tm < 2; tm++) {
        #pragma unroll
        for (int tn = 0; tn < 2; tn++) {
            const int mrow = wm + tm * 16 + gr;
            const int ncol = wn + tn * 8 + gc * 2;
            const float* ac = acc[tm][tn];
            if (mode == 2) {
                *reinterpret_cast<float2*>(Cout + (size_t)mrow * 64 + ncol) =
                    make_float2(ac[0], ac[1]);
                *reinterpret_cast<float2*>(Cout + (size_t)(mrow + 8) * 64 + ncol) =
                    make_float2(ac[2], ac[3]);
            } else {
                const size_t i0 = (size_t)(bm + mrow) * HIDP + bn + ncol;
                const size_t i1 = (size_t)(bm + mrow + 8) * HIDP + bn + ncol;
                if (mode == 0) {
                    *reinterpret_cast<float2*>(C + i0) = make_float2(alpha * ac[0], alpha * ac[1]);
                    *reinterpret_cast<float2*>(C + i1) = make_float2(alpha * ac[2], alpha * ac[3]);
                } else {
                    float2 d0 = *reinterpret_cast<const float2*>(Dm + i0);
                    float2 d1 = *reinterpret_cast<const float2*>(Dm + i1);
                    *reinterpret_cast<float2*>(C + i0) = make_float2(d0.x - ac[0], d0.y - ac[1]);
                    *reinterpret_cast<float2*>(C + i1) = make_float2(d1.x - ac[2], d1.y - ac[3]);
                }
            }
        }
    }
}

// ============ AugT builder: AugT[c][p], c<513 real, rest zero ============
__global__ void transpose_aug(const float* __restrict__ X, const float* __restrict__ y,
                              float* __restrict__ AugT)
{
    __shared__ float tile[32][33];
    const int c0 = blockIdx.x * 32;
    const int p0 = blockIdx.y * 32;
    const int tx = threadIdx.x, ty = threadIdx.y;
    #pragma unroll
    for (int j = 0; j < 4; j++) {
        const int p = p0 + ty + j * 8;
        const int c = c0 + tx;
        float v = 0.f;
        if (c < D_DIM)       v = X[(size_t)p * D_DIM + c];
        else if (c == D_DIM) v = y[p];
        tile[ty + j * 8][tx] = v;
    }
    __syncthreads();
    #pragma unroll
    for (int j = 0; j < 4; j++) {
        const int c = c0 + ty + j * 8;
        AugT[(size_t)c * P_CTX + p0 + tx] = tile[tx][ty + j * 8];
    }
}

// reduce syrk partials, scatter symmetrically
__global__ void reduce_sym(const float* __restrict__ Spart, float* __restrict__ S)
{
    const int q = blockIdx.x;
    const int e = blockIdx.y * 256 + threadIdx.x;   // 0..4095
    int ti = 0, rem = q;
    while (rem >= NTILE - ti) { rem -= NTILE - ti; ti++; }
    const int tj = ti + rem;
    const int mi = e >> 6, nj = e & 63;
    float s = 0.f;
    #pragma unroll
    for (int z = 0; z < NZ; z++)
        s += Spart[((size_t)z * NPAIR + q) * 4096 + e];
    const int gm = ti * 64 + mi, gn = tj * 64 + nj;
    S[(size_t)gm * HIDP + gn] = s;
    S[(size_t)gn * HIDP + gm] = s;
}

// ---------------- padded builders ----------------
__global__ void build_wxa(const float* __restrict__ Wx, const float* __restrict__ wy,
                          float* __restrict__ dst)
{
    int idx = blockIdx.x * 256 + threadIdx.x;
    if (idx >= HIDP2) return;
    int r = idx / HIDP, c = idx % HIDP;
    float v = 0.f;
    if (r < HID) {
        if (c < D_DIM) v = Wx[(size_t)r * D_DIM + c];
        else if (c == D_DIM) v = wy[r];
    }
    dst[idx] = v;
}
__global__ void pad_copy(const float* __restrict__ src, float* __restrict__ dst)
{
    int idx = blockIdx.x * 256 + threadIdx.x;
    if (idx >= HIDP2) return;
    int r = idx / HIDP, c = idx % HIDP;
    dst[idx] = (r < HID && c < HID) ? src[(size_t)r * HID + c] : 0.f;
}
__global__ void pad_copy_T(const float* __restrict__ src, float* __restrict__ dst)
{
    int idx = blockIdx.x * 256 + threadIdx.x;
    if (idx >= HIDP2) return;
    int r = idx / HIDP, c = idx % HIDP;
    dst[idx] = (r < HID && c < HID) ? src[(size_t)c * HID + r] : 0.f;
}

// ---------------- vector tail (fp32 exact) ----------------
__global__ void copy_vec(const float* __restrict__ src, float* __restrict__ dst, int n)
{
    int i = blockIdx.x * 256 + threadIdx.x;
    if (i < n) dst[i] = src[i];
}
__global__ void gemv_t_add(const float* __restrict__ A, const float* __restrict__ uin,
                           float* __restrict__ uout)
{
    int j = blockIdx.x * 256 + threadIdx.x;
    if (j >= HID) return;
    float s = uin[j];
    #pragma unroll 4
    for (int i = 0; i < HID; i++) s += A[(size_t)i * HIDP + j] * uin[i];
    uout[j] = s;
}
__global__ void gemv_wx_t(const float* __restrict__ Wx, const float* __restrict__ u,
                          float* __restrict__ d)
{
    int j = blockIdx.x * 256 + threadIdx.x;
    if (j >= D_DIM) return;
    float s = 0.f;
    #pragma unroll 4
    for (int i = 0; i < HID; i++) s += Wx[(size_t)i * D_DIM + j] * u[i];
    d[j] = s;
}
__global__ void out_k(const float* __restrict__ Xs, const float* __restrict__ d,
                      float* __restrict__ out)
{
    int k = blockIdx.x * 8 + (threadIdx.x >> 5);
    int lane = threadIdx.x & 31;
    if (k >= KTEST) return;
    const float* row = Xs + (size_t)k * D_DIM;
    float s = 0.f;
    #pragma unroll 4
    for (int c = lane; c < D_DIM; c += 32) s += row[c] * d[c];
    #pragma unroll
    for (int o = 16; o > 0; o >>= 1) s += __shfl_xor_sync(0xFFFFFFFFu, s, o);
    if (lane == 0) out[k] = s;
}

// ---------------- host orchestration ----------------
static float* sym_addr(const void* sym) {
    void* p = nullptr;
    cudaGetSymbolAddress(&p, sym);
    return (float*)p;
}

extern "C" void kernel_launch(void* const* d_in, const int* in_sizes, int n_in,
                              void* d_out, int out_size)
{
    const float* X  = (const float*)d_in[0];
    const float* y  = (const float*)d_in[1];
    const float* Xs = (const float*)d_in[2];
    const float* Wx = (const float*)d_in[3];
    const float* wy = (const float*)d_in[4];
    const float* wo = (const float*)d_in[5];
    const float* Wk = (const float*)d_in[6];
    const float* Wq = (const float*)d_in[7];
    const float* Wv = (const float*)d_in[8];
    float* out = (float*)d_out;

    float* AugT  = sym_addr(g_AugT);
    float* Spart = sym_addr(g_Spart);
    float* S     = sym_addr(g_S);
    float* Wxa   = sym_addr(g_Wxa);
    float* WqT   = sym_addr(g_WqT);
    float* WkT   = sym_addr(g_WkT);
    float* WvP   = sym_addr(g_WvP);
    float* F     = sym_addr(g_F);
    float* G     = sym_addr(g_G);
    float* T     = sym_addr(g_T);
    float* T2    = sym_addr(g_T2);
    float* A     = sym_addr(g_A);
    float* u     = sym_addr(g_u);
    float* dv    = sym_addr(g_d);

    const dim3 g99(NTILE, NTILE);
    const int eb = (HIDP2 + 255) / 256;
    const float scale = 1.0f / (LDEPTH * (float)P_CTX);
    const int KCH = HIDP / KC;   // 18

    // 1) AugT + tf32 split-K syrk -> S
    transpose_aug<<<dim3(HIDP / 32, P_CTX / 32), dim3(32, 8)>>>(X, y, AugT);
    mma_gemm<<<dim3(NPAIR, 1, NZ), 256>>>(AugT, P_CTX, AugT, P_CTX,
                                          Spart, nullptr, ZCHUNK / KC, 1.f, 2);
    reduce_sym<<<dim3(NPAIR, 16), 256>>>(Spart, S);

    // 2) padded operands
    build_wxa <<<eb, 256>>>(Wx, wy, Wxa);
    pad_copy_T<<<eb, 256>>>(Wq, WqT);
    pad_copy_T<<<eb, 256>>>(Wk, WkT);
    pad_copy  <<<eb, 256>>>(Wv, WvP);

    // 3) G0 = Wxa S Wxa^T ; F = E^T = Wq^T Wk   (S, G symmetric => B^T form ok)
    mma_gemm<<<g99, 256>>>(Wxa, HIDP, S,   HIDP, T, nullptr, KCH, 1.f, 0);
    mma_gemm<<<g99, 256>>>(T,   HIDP, Wxa, HIDP, G, nullptr, KCH, 1.f, 0);
    mma_gemm<<<g99, 256>>>(WqT, HIDP, WkT, HIDP, F, nullptr, KCH, 1.f, 0);

    // 4) layer loop (G symmetric): Tt = F·G^T = (G E)^T ; Al = scale·Wv·Tt^T;
    //    T2 = G - Al·G^T ; G = T2 - T2·Al^T
    for (int l = 0; l < LDEPTH; l++) {
        float* Al = A + (size_t)l * HIDP2;
        mma_gemm<<<g99, 256>>>(F,   HIDP, G,  HIDP, T,  nullptr, KCH, 1.f,   0);
        mma_gemm<<<g99, 256>>>(WvP, HIDP, T,  HIDP, Al, nullptr, KCH, scale, 0);
        mma_gemm<<<g99, 256>>>(Al,  HIDP, G,  HIDP, T2, G,       KCH, 1.f,   1);
        mma_gemm<<<g99, 256>>>(T2,  HIDP, Al, HIDP, G,  T2,      KCH, 1.f,   1);
    }

    // 5) u = prod (I+A_l)^T w_o
    copy_vec<<<3, 256>>>(wo, u, HID);
    for (int i = 0; i < LDEPTH; i++) {
        int l = LDEPTH - 1 - i;
        int cur = i & 1;
        gemv_t_add<<<3, 256>>>(A + (size_t)l * HIDP2, u + cur * HID, u + (cur ^ 1) * HID);
    }

    // 6) d = Wx^T u ; out = X_star d
    gemv_wx_t<<<2, 256>>>(Wx, u, dv);
    out_k<<<KTEST / 8, 256>>>(Xs, dv, out);
}